// round 2
// baseline (speedup 1.0000x reference)
#include <cuda_runtime.h>

#define NMAX 50000
#define EMAX 800000
#define FDIM 128

// ---------------- scratch (static device globals; no allocation) ------------
__device__ __align__(256) float g_h[(size_t)NMAX * FDIM];   // 25.6 MB (GEMM out / AGG in)
__device__ __align__(256) float g_t[(size_t)NMAX * FDIM];   // 25.6 MB (AGG out / next GEMM in)
__device__ float g_dinv[NMAX];
__device__ int   g_hist[NMAX];
__device__ int   g_start[NMAX + 1];
__device__ int   g_fill[NMAX];
__device__ int   g_erow[EMAX];
__device__ float g_enorm[EMAX];
__device__ int   g_bsum[256];
__device__ int   g_is64;

// ---------------- dtype detection (int32 vs int64 edge_index) ---------------
// If data is int64 (values in [0, 50000)), every odd 32-bit word is 0.
// If int32, odd words are random node ids; all-zero over 2048 samples is
// impossible in practice.
__global__ void detect_kernel(const int* __restrict__ w, int E) {
    __shared__ int any;
    if (threadIdx.x == 0) any = 0;
    __syncthreads();
    int words = 2 * E; if (words > 4096) words = 4096;
    int local = 0;
    for (int i = 1 + 2 * (int)threadIdx.x; i < words; i += 2 * blockDim.x)
        local |= w[i];
    if (local) atomicOr(&any, 1);
    __syncthreads();
    if (threadIdx.x == 0) g_is64 = (any == 0) ? 1 : 0;
}

__device__ __forceinline__ int edge_at(const void* ep, long long idx) {
    return g_is64 ? (int)((const long long*)ep)[idx] : ((const int*)ep)[idx];
}

// ---------------- degree / norm -------------------------------------------
__global__ void hist_init(int n) {
    int i = blockIdx.x * blockDim.x + threadIdx.x;
    if (i < n) g_hist[i] = 0;
}

__global__ void hist_count(const void* __restrict__ ep, int E) {
    int e = blockIdx.x * blockDim.x + threadIdx.x;
    if (e >= E) return;
    int col = edge_at(ep, (long long)E + e);
    atomicAdd(&g_hist[col], 1);
}

__global__ void dinv_kernel(int n) {
    int i = blockIdx.x * blockDim.x + threadIdx.x;
    if (i >= n) return;
    // deg includes the self-loop -> hist + 1 (always > 0)
    g_dinv[i] = rsqrtf((float)(g_hist[i] + 1));
}

// ---------------- exclusive scan of g_hist -> g_start (3 passes) -----------
__global__ void scan_pass1(int n) {   // per-block sums, 512 elems/block
    __shared__ int s[512];
    int i = blockIdx.x * 512 + threadIdx.x;
    s[threadIdx.x] = (i < n) ? g_hist[i] : 0;
    __syncthreads();
    for (int off = 256; off > 0; off >>= 1) {
        if (threadIdx.x < off) s[threadIdx.x] += s[threadIdx.x + off];
        __syncthreads();
    }
    if (threadIdx.x == 0) g_bsum[blockIdx.x] = s[0];
}

__global__ void scan_pass2(int nb, int n) {  // serial scan of block sums
    if (threadIdx.x == 0 && blockIdx.x == 0) {
        int acc = 0;
        for (int i = 0; i < nb; i++) { int v = g_bsum[i]; g_bsum[i] = acc; acc += v; }
        g_start[n] = acc;
    }
}

__global__ void scan_pass3(int n) {   // local exclusive scan + block offset
    __shared__ int s[512];
    int i = blockIdx.x * 512 + threadIdx.x;
    int v = (i < n) ? g_hist[i] : 0;
    s[threadIdx.x] = v;
    __syncthreads();
    for (int off = 1; off < 512; off <<= 1) {
        int t = (threadIdx.x >= off) ? s[threadIdx.x - off] : 0;
        __syncthreads();
        s[threadIdx.x] += t;
        __syncthreads();
    }
    if (i < n) g_start[i] = s[threadIdx.x] - v + g_bsum[blockIdx.x];
}

// ---------------- CSR fill --------------------------------------------------
__global__ void fill_init(int n) {
    int i = blockIdx.x * blockDim.x + threadIdx.x;
    if (i < n) g_fill[i] = g_start[i];
}

__global__ void fill_edges(const void* __restrict__ ep, int E) {
    int e = blockIdx.x * blockDim.x + threadIdx.x;
    if (e >= E) return;
    int r = edge_at(ep, e);
    int c = edge_at(ep, (long long)E + e);
    int pos = atomicAdd(&g_fill[c], 1);
    g_erow[pos]  = r;
    g_enorm[pos] = g_dinv[r] * g_dinv[c];
}

// ---------------- GEMM: g_h[M,128] = A[M,128] * B[128,128] -----------------
// 128x128 block tile, 8x8 micro-tile per thread, K chunked by 32.
// Destination is ALWAYS the g_h scratch global (avoids host-side symbol lookup).
__global__ __launch_bounds__(256, 2)
void gemm_128(const float* __restrict__ A, const float* __restrict__ B, int M) {
    __shared__ float As[32][132];   // As[k][r] (transposed A tile)
    __shared__ float Bs[32][128];   // Bs[k][c]
    int tid = threadIdx.x;
    int tx = tid & 15;              // col group (0..15)
    int ty = tid >> 4;              // row group (0..15)
    int row0 = blockIdx.x * 128;

    float acc[8][8];
#pragma unroll
    for (int i = 0; i < 8; i++)
#pragma unroll
        for (int j = 0; j < 8; j++) acc[i][j] = 0.0f;

    for (int k0 = 0; k0 < 128; k0 += 32) {
        // load A tile (transposed): 128 rows x 32 k
#pragma unroll
        for (int it = 0; it < 4; it++) {
            int idx = tid + it * 256;       // 0..1023 float4 slots
            int r   = idx & 127;
            int k4  = idx >> 7;             // 0..7
            float4 v = make_float4(0.f, 0.f, 0.f, 0.f);
            int gr = row0 + r;
            if (gr < M)
                v = *(const float4*)(A + (size_t)gr * 128 + k0 + k4 * 4);
            As[k4 * 4 + 0][r] = v.x;
            As[k4 * 4 + 1][r] = v.y;
            As[k4 * 4 + 2][r] = v.z;
            As[k4 * 4 + 3][r] = v.w;
        }
        // load B tile: 32 x 128
#pragma unroll
        for (int it = 0; it < 4; it++) {
            int idx = tid + it * 256;       // float4 index in 32x32(f4)
            int kk = idx >> 5;
            int c4 = idx & 31;
            *(float4*)&Bs[kk][c4 * 4] =
                *(const float4*)(B + (size_t)(k0 + kk) * 128 + c4 * 4);
        }
        __syncthreads();
#pragma unroll
        for (int kk = 0; kk < 32; kk++) {
            float a[8], b[8];
            *(float4*)(a)     = *(const float4*)&As[kk][ty * 8];
            *(float4*)(a + 4) = *(const float4*)&As[kk][ty * 8 + 4];
            *(float4*)(b)     = *(const float4*)&Bs[kk][tx * 8];
            *(float4*)(b + 4) = *(const float4*)&Bs[kk][tx * 8 + 4];
#pragma unroll
            for (int i = 0; i < 8; i++)
#pragma unroll
                for (int j = 0; j < 8; j++) acc[i][j] += a[i] * b[j];
        }
        __syncthreads();
    }

#pragma unroll
    for (int i = 0; i < 8; i++) {
        int gr = row0 + ty * 8 + i;
        if (gr < M) {
            float* cp = g_h + (size_t)gr * 128 + tx * 8;
            *(float4*)cp       = make_float4(acc[i][0], acc[i][1], acc[i][2], acc[i][3]);
            *(float4*)(cp + 4) = make_float4(acc[i][4], acc[i][5], acc[i][6], acc[i][7]);
        }
    }
}

// ---------------- aggregation: warp per node, CSR gather -------------------
// Reads g_h, writes g_t.
__global__ void agg_kernel(const float* __restrict__ bias, int n) {
    int gw   = (blockIdx.x * blockDim.x + threadIdx.x) >> 5;
    int lane = threadIdx.x & 31;
    if (gw >= n) return;
    const float4* base = (const float4*)g_h;
    float di = g_dinv[gw];
    float w0 = di * di;
    float4 v = __ldg(&base[(size_t)gw * 32 + lane]);
    float4 acc = make_float4(w0 * v.x, w0 * v.y, w0 * v.z, w0 * v.w);
    int s = g_start[gw], t = g_start[gw + 1];
    int e = s;
    for (; e + 1 < t; e += 2) {
        int   r0 = g_erow[e],     r1 = g_erow[e + 1];
        float n0 = g_enorm[e],    n1 = g_enorm[e + 1];
        float4 u0 = __ldg(&base[(size_t)r0 * 32 + lane]);
        float4 u1 = __ldg(&base[(size_t)r1 * 32 + lane]);
        acc.x += n0 * u0.x + n1 * u1.x;
        acc.y += n0 * u0.y + n1 * u1.y;
        acc.z += n0 * u0.z + n1 * u1.z;
        acc.w += n0 * u0.w + n1 * u1.w;
    }
    if (e < t) {
        int r = g_erow[e]; float w = g_enorm[e];
        float4 u = __ldg(&base[(size_t)r * 32 + lane]);
        acc.x += w * u.x; acc.y += w * u.y; acc.z += w * u.z; acc.w += w * u.w;
    }
    float4 b = __ldg(&((const float4*)bias)[lane]);
    acc.x += b.x; acc.y += b.y; acc.z += b.z; acc.w += b.w;
    ((float4*)g_t)[(size_t)gw * 32 + lane] = acc;
}

// ---------------- copy g_t -> (used as next GEMM A input) is implicit ------
// gemm takes A pointer; for layer 2 A must be g_t. We handle this by a tiny
// dispatcher kernel-free approach: gemm_128_t reads g_t directly.
__global__ __launch_bounds__(256, 2)
void gemm_128_t(const float* __restrict__ B, int M) {
    __shared__ float As[32][132];
    __shared__ float Bs[32][128];
    int tid = threadIdx.x;
    int tx = tid & 15;
    int ty = tid >> 4;
    int row0 = blockIdx.x * 128;
    const float* A = g_t;

    float acc[8][8];
#pragma unroll
    for (int i = 0; i < 8; i++)
#pragma unroll
        for (int j = 0; j < 8; j++) acc[i][j] = 0.0f;

    for (int k0 = 0; k0 < 128; k0 += 32) {
#pragma unroll
        for (int it = 0; it < 4; it++) {
            int idx = tid + it * 256;
            int r   = idx & 127;
            int k4  = idx >> 7;
            float4 v = make_float4(0.f, 0.f, 0.f, 0.f);
            int gr = row0 + r;
            if (gr < M)
                v = *(const float4*)(A + (size_t)gr * 128 + k0 + k4 * 4);
            As[k4 * 4 + 0][r] = v.x;
            As[k4 * 4 + 1][r] = v.y;
            As[k4 * 4 + 2][r] = v.z;
            As[k4 * 4 + 3][r] = v.w;
        }
#pragma unroll
        for (int it = 0; it < 4; it++) {
            int idx = tid + it * 256;
            int kk = idx >> 5;
            int c4 = idx & 31;
            *(float4*)&Bs[kk][c4 * 4] =
                *(const float4*)(B + (size_t)(k0 + kk) * 128 + c4 * 4);
        }
        __syncthreads();
#pragma unroll
        for (int kk = 0; kk < 32; kk++) {
            float a[8], b[8];
            *(float4*)(a)     = *(const float4*)&As[kk][ty * 8];
            *(float4*)(a + 4) = *(const float4*)&As[kk][ty * 8 + 4];
            *(float4*)(b)     = *(const float4*)&Bs[kk][tx * 8];
            *(float4*)(b + 4) = *(const float4*)&Bs[kk][tx * 8 + 4];
#pragma unroll
            for (int i = 0; i < 8; i++)
#pragma unroll
                for (int j = 0; j < 8; j++) acc[i][j] += a[i] * b[j];
        }
        __syncthreads();
    }

#pragma unroll
    for (int i = 0; i < 8; i++) {
        int gr = row0 + ty * 8 + i;
        if (gr < M) {
            float* cp = g_h + (size_t)gr * 128 + tx * 8;
            *(float4*)cp       = make_float4(acc[i][0], acc[i][1], acc[i][2], acc[i][3]);
            *(float4*)(cp + 4) = make_float4(acc[i][4], acc[i][5], acc[i][6], acc[i][7]);
        }
    }
}

// ---------------- final projection: out[N,8] = g_t[N,128] @ Wfc + bfc ------
__global__ void fc_kernel(const float* __restrict__ Wfc,
                          const float* __restrict__ bfc, float* __restrict__ out, int n) {
    __shared__ float wsT[8 * 128];   // transposed: wsT[c*128 + k]
    __shared__ float bs[8];
    for (int i = threadIdx.x; i < 1024; i += blockDim.x) {
        int k = i >> 3, c = i & 7;
        wsT[c * 128 + k] = Wfc[i];
    }
    if (threadIdx.x < 8) bs[threadIdx.x] = bfc[threadIdx.x];
    __syncthreads();
    int gw   = (blockIdx.x * blockDim.x + threadIdx.x) >> 5;
    int lane = threadIdx.x & 31;
    if (gw >= n) return;
    float4 v = ((const float4*)g_t)[(size_t)gw * 32 + lane];
#pragma unroll
    for (int c = 0; c < 8; c++) {
        float4 w = *(const float4*)&wsT[c * 128 + lane * 4];
        float p = v.x * w.x + v.y * w.y + v.z * w.z + v.w * w.w;
#pragma unroll
        for (int off = 16; off > 0; off >>= 1)
            p += __shfl_xor_sync(0xffffffffu, p, off);
        if (lane == 0) out[(size_t)gw * 8 + c] = p + bs[c];
    }
}

// ---------------- launch ----------------------------------------------------
extern "C" void kernel_launch(void* const* d_in, const int* in_sizes, int n_in,
                              void* d_out, int out_size) {
    const float* x   = (const float*)d_in[0];
    const void*  ei  = d_in[1];
    const float* W1  = (const float*)d_in[2];
    const float* b1  = (const float*)d_in[3];
    const float* W2  = (const float*)d_in[4];
    const float* b2  = (const float*)d_in[5];
    const float* Wfc = (const float*)d_in[6];
    const float* bfc = (const float*)d_in[7];
    float* out = (float*)d_out;

    int N = in_sizes[0] / FDIM;
    int E = in_sizes[1] / 2;
    int nb = (N + 511) / 512;

    int tB = 256;
    int gN = (N + tB - 1) / tB;
    int gE = (E + tB - 1) / tB;
    int gW = (N * 32 + tB - 1) / tB;   // warp-per-node grids
    int gM = (N + 127) / 128;

    detect_kernel<<<1, 256>>>((const int*)ei, E);
    hist_init<<<gN, tB>>>(N);
    hist_count<<<gE, tB>>>(ei, E);
    dinv_kernel<<<gN, tB>>>(N);
    scan_pass1<<<nb, 512>>>(N);
    scan_pass2<<<1, 32>>>(nb, N);
    scan_pass3<<<nb, 512>>>(N);
    fill_init<<<gN, tB>>>(N);
    fill_edges<<<gE, tB>>>(ei, E);

    gemm_128<<<gM, 256>>>(x, W1, N);      // x @ W1        -> g_h
    agg_kernel<<<gW, tB>>>(b1, N);        // aggregate g_h -> g_t (+b1)
    gemm_128_t<<<gM, 256>>>(W2, N);       // g_t @ W2      -> g_h
    agg_kernel<<<gW, tB>>>(b2, N);        // aggregate g_h -> g_t (+b2)
    fc_kernel<<<gW, tB>>>(Wfc, bfc, out, N);
}

// round 5
// speedup vs baseline: 1.2000x; 1.2000x over previous
#include <cuda_runtime.h>
#include <cuda_bf16.h>
#include <cstdint>

#define NMAX 50000
#define EMAX 800000
#define FDIM 128

// ---------------- scratch (static device globals; no allocation) ------------
__device__ __align__(256) float g_h[(size_t)NMAX * FDIM];   // 25.6 MB (GEMM out / AGG in)
__device__ __align__(256) float g_t[(size_t)NMAX * FDIM];   // 25.6 MB (AGG out / next GEMM in)
__device__ float g_dinv[NMAX];
__device__ int   g_hist[NMAX];
__device__ int   g_start[NMAX + 1];
__device__ int   g_fill[NMAX];
__device__ int   g_erow[EMAX];
__device__ float g_enorm[EMAX];
__device__ int   g_bsum[256];
__device__ int   g_is64;
// W split planes, transposed to BT[n][k] bf16 raw bits: [layer][16384]
__device__ unsigned short g_whi[2][FDIM * FDIM];
__device__ unsigned short g_wlo[2][FDIM * FDIM];

// ---------------- helpers ----------------------------------------------------
__device__ __forceinline__ uint32_t smem_u32(const void* p) {
    uint32_t a;
    asm("{ .reg .u64 t; cvta.to.shared.u64 t, %1; cvt.u32.u64 %0, t; }" : "=r"(a) : "l"(p));
    return a;
}
__device__ __forceinline__ void ldm_x4(uint32_t (&r)[4], uint32_t addr) {
    asm volatile("ldmatrix.sync.aligned.m8n8.x4.shared.b16 {%0,%1,%2,%3}, [%4];"
                 : "=r"(r[0]), "=r"(r[1]), "=r"(r[2]), "=r"(r[3]) : "r"(addr));
}
__device__ __forceinline__ void mma_bf16(float (&c)[4], const uint32_t (&a)[4],
                                         const uint32_t b0, const uint32_t b1) {
    asm volatile(
        "mma.sync.aligned.m16n8k16.row.col.f32.bf16.bf16.f32 "
        "{%0,%1,%2,%3}, {%4,%5,%6,%7}, {%8,%9}, {%0,%1,%2,%3};"
        : "+f"(c[0]), "+f"(c[1]), "+f"(c[2]), "+f"(c[3])
        : "r"(a[0]), "r"(a[1]), "r"(a[2]), "r"(a[3]), "r"(b0), "r"(b1));
}

// ---------------- dtype detection (int32 vs int64 edge_index) ---------------
__global__ void detect_kernel(const int* __restrict__ w, int E) {
    __shared__ int any;
    if (threadIdx.x == 0) any = 0;
    __syncthreads();
    int words = 2 * E; if (words > 4096) words = 4096;
    int local = 0;
    for (int i = 1 + 2 * (int)threadIdx.x; i < words; i += 2 * blockDim.x)
        local |= w[i];
    if (local) atomicOr(&any, 1);
    __syncthreads();
    if (threadIdx.x == 0) g_is64 = (any == 0) ? 1 : 0;
}

__device__ __forceinline__ int edge_at(const void* ep, long long idx) {
    return g_is64 ? (int)((const long long*)ep)[idx] : ((const int*)ep)[idx];
}

// ---------------- degree / norm -------------------------------------------
__global__ void hist_init(int n) {
    int i = blockIdx.x * blockDim.x + threadIdx.x;
    if (i < n) g_hist[i] = 0;
}
__global__ void hist_count(const void* __restrict__ ep, int E) {
    int e = blockIdx.x * blockDim.x + threadIdx.x;
    if (e >= E) return;
    atomicAdd(&g_hist[edge_at(ep, (long long)E + e)], 1);
}
__global__ void dinv_kernel(int n) {
    int i = blockIdx.x * blockDim.x + threadIdx.x;
    if (i >= n) return;
    g_dinv[i] = rsqrtf((float)(g_hist[i] + 1));
}

// ---------------- exclusive scan of g_hist -> g_start -----------------------
__global__ void scan_pass1(int n) {
    __shared__ int s[512];
    int i = blockIdx.x * 512 + threadIdx.x;
    s[threadIdx.x] = (i < n) ? g_hist[i] : 0;
    __syncthreads();
    for (int off = 256; off > 0; off >>= 1) {
        if (threadIdx.x < off) s[threadIdx.x] += s[threadIdx.x + off];
        __syncthreads();
    }
    if (threadIdx.x == 0) g_bsum[blockIdx.x] = s[0];
}
__global__ void scan_pass2(int nb, int n) {
    if (threadIdx.x == 0 && blockIdx.x == 0) {
        int acc = 0;
        for (int i = 0; i < nb; i++) { int v = g_bsum[i]; g_bsum[i] = acc; acc += v; }
        g_start[n] = acc;
    }
}
__global__ void scan_pass3(int n) {
    __shared__ int s[512];
    int i = blockIdx.x * 512 + threadIdx.x;
    int v = (i < n) ? g_hist[i] : 0;
    s[threadIdx.x] = v;
    __syncthreads();
    for (int off = 1; off < 512; off <<= 1) {
        int t = (threadIdx.x >= off) ? s[threadIdx.x - off] : 0;
        __syncthreads();
        s[threadIdx.x] += t;
        __syncthreads();
    }
    if (i < n) {
        int ex = s[threadIdx.x] - v + g_bsum[blockIdx.x];
        g_start[i] = ex;
        g_fill[i]  = ex;   // fused fill_init
    }
}

// ---------------- CSR fill --------------------------------------------------
__global__ void fill_edges(const void* __restrict__ ep, int E) {
    int e = blockIdx.x * blockDim.x + threadIdx.x;
    if (e >= E) return;
    int r = edge_at(ep, e);
    int c = edge_at(ep, (long long)E + e);
    int pos = atomicAdd(&g_fill[c], 1);
    g_erow[pos]  = r;
    g_enorm[pos] = g_dinv[r] * g_dinv[c];
}

// ---------------- W prep: transpose + bf16 split -----------------------------
// g_whi[m][n*128+k] = bf16(W[k][n]);  g_wlo = bf16(W[k][n] - hi)
__global__ void prep_w(const float* __restrict__ W1, const float* __restrict__ W2) {
    int idx = blockIdx.x * blockDim.x + threadIdx.x;   // 0 .. 32767
    if (idx >= 2 * FDIM * FDIM) return;
    int m = idx >> 14;
    int r = idx & 16383;
    int k = r >> 7, n = r & 127;
    float v = (m ? W2 : W1)[k * FDIM + n];
    __nv_bfloat16 hi = __float2bfloat16(v);
    __nv_bfloat16 lo = __float2bfloat16(v - __bfloat162float(hi));
    g_whi[m][n * FDIM + k] = __bfloat16_as_ushort(hi);
    g_wlo[m][n * FDIM + k] = __bfloat16_as_ushort(lo);
}

// ---------------- mma.sync GEMM: g_h[M,128] = A[M,128] @ W ------------------
// Split-bf16 (hi/lo), 3 HMMA terms, fp32 accumulate.
// smem: A hi/lo + BT hi/lo, each 128 x 136(pad) bf16 (272B rows, 16B-aligned,
// 4-bank row shift -> conflict-free ldmatrix).
#define TROW 272                      // padded row stride in bytes (136 bf16)
#define PL_BYTES (128 * TROW)         // 34816 per plane
#define SMEM_GEMM (4 * PL_BYTES)      // 139264

__global__ __launch_bounds__(256, 1)
void gemm_mma(const float* __restrict__ Aparam, int use_gt, int layer, int M) {
    extern __shared__ char smem[];
    uint32_t sAhi = smem_u32(smem);
    uint32_t sAlo = sAhi + PL_BYTES;
    uint32_t sBhi = sAhi + 2 * PL_BYTES;
    uint32_t sBlo = sAhi + 3 * PL_BYTES;

    int tid  = threadIdx.x;
    int wid  = tid >> 5;
    int lane = tid & 31;
    int row0 = blockIdx.x * 128;
    const float* A = use_gt ? (const float*)g_t : Aparam;
    const unsigned short* WH = g_whi[layer];
    const unsigned short* WL = g_wlo[layer];

    // ---- fill smem: 4096 slots = (row 0..127) x (k4 0..31) ----
#pragma unroll 4
    for (int it = 0; it < 16; it++) {
        int slot = tid + it * 256;
        int r  = slot >> 5;
        int k  = (slot & 31) * 4;
        uint32_t off = (uint32_t)(r * TROW + k * 2);

        // A: fp32 -> hi/lo bf16
        float4 v = make_float4(0.f, 0.f, 0.f, 0.f);
        int gr = row0 + r;
        if (gr < M) v = *(const float4*)(A + (size_t)gr * 128 + k);
        __nv_bfloat16 h0 = __float2bfloat16(v.x), h1 = __float2bfloat16(v.y);
        __nv_bfloat16 h2 = __float2bfloat16(v.z), h3 = __float2bfloat16(v.w);
        __nv_bfloat16 l0 = __float2bfloat16(v.x - __bfloat162float(h0));
        __nv_bfloat16 l1 = __float2bfloat16(v.y - __bfloat162float(h1));
        __nv_bfloat16 l2 = __float2bfloat16(v.z - __bfloat162float(h2));
        __nv_bfloat16 l3 = __float2bfloat16(v.w - __bfloat162float(h3));
        uint2 hA = make_uint2(((uint32_t)__bfloat16_as_ushort(h1) << 16) | __bfloat16_as_ushort(h0),
                              ((uint32_t)__bfloat16_as_ushort(h3) << 16) | __bfloat16_as_ushort(h2));
        uint2 lA = make_uint2(((uint32_t)__bfloat16_as_ushort(l1) << 16) | __bfloat16_as_ushort(l0),
                              ((uint32_t)__bfloat16_as_ushort(l3) << 16) | __bfloat16_as_ushort(l2));
        *(uint2*)(smem + (sAhi - smem_u32(smem)) + off) = hA;   // same as below; keep simple:
        *(uint2*)(smem + PL_BYTES + off) = lA;

        // B: pre-split bf16 copy (r is the n index)
        *(uint2*)(smem + 2 * PL_BYTES + off) = *(const uint2*)(WH + r * 128 + k);
        *(uint2*)(smem + 3 * PL_BYTES + off) = *(const uint2*)(WL + r * 128 + k);
    }
    __syncthreads();

    // ---- warp tiles: 4 m-groups x 2 n-groups; warp = 32 rows x 64 cols ----
    int m0 = (wid & 3) * 32;
    int n0 = (wid >> 2) * 64;
    int arow  = lane & 15;
    int acol  = (lane >> 4) << 3;
    int l7    = lane & 7;
    int halfq = lane >> 3;                       // 0..3
    int bn    = ((halfq >> 1) << 3) + l7;        // n offset within 16-row pair
    int bk    = (halfq & 1) << 3;                // k offset 0/8

    float c[2][8][4];
#pragma unroll
    for (int mt = 0; mt < 2; mt++)
#pragma unroll
        for (int j = 0; j < 8; j++)
#pragma unroll
            for (int q = 0; q < 4; q++) c[mt][j][q] = 0.f;

#pragma unroll
    for (int kc = 0; kc < 8; kc++) {
        int k0 = kc * 16;
        uint32_t ahi[2][4], alo[2][4];
#pragma unroll
        for (int mt = 0; mt < 2; mt++) {
            uint32_t off = (uint32_t)((m0 + mt * 16 + arow) * TROW + (k0 + acol) * 2);
            ldm_x4(ahi[mt], sAhi + off);
            ldm_x4(alo[mt], sAlo + off);
        }
        uint32_t bhi[8][2], blo[8][2];
#pragma unroll
        for (int jp = 0; jp < 4; jp++) {
            uint32_t off = (uint32_t)((n0 + jp * 16 + bn) * TROW + (k0 + bk) * 2);
            uint32_t r4[4];
            ldm_x4(r4, sBhi + off);
            bhi[jp * 2][0] = r4[0]; bhi[jp * 2][1] = r4[1];
            bhi[jp * 2 + 1][0] = r4[2]; bhi[jp * 2 + 1][1] = r4[3];
            ldm_x4(r4, sBlo + off);
            blo[jp * 2][0] = r4[0]; blo[jp * 2][1] = r4[1];
            blo[jp * 2 + 1][0] = r4[2]; blo[jp * 2 + 1][1] = r4[3];
        }
#pragma unroll
        for (int mt = 0; mt < 2; mt++)
#pragma unroll
            for (int j = 0; j < 8; j++) {
                mma_bf16(c[mt][j], ahi[mt], bhi[j][0], bhi[j][1]);
                mma_bf16(c[mt][j], alo[mt], bhi[j][0], bhi[j][1]);
                mma_bf16(c[mt][j], ahi[mt], blo[j][0], blo[j][1]);
            }
    }

    // ---- epilogue ----
    int g = lane >> 2, t = lane & 3;
#pragma unroll
    for (int mt = 0; mt < 2; mt++) {
        int rlo = row0 + m0 + mt * 16 + g;
#pragma unroll
        for (int j = 0; j < 8; j++) {
            int col = n0 + j * 8 + t * 2;
            if (rlo < M)
                *(float2*)(g_h + (size_t)rlo * 128 + col) = make_float2(c[mt][j][0], c[mt][j][1]);
            if (rlo + 8 < M)
                *(float2*)(g_h + (size_t)(rlo + 8) * 128 + col) = make_float2(c[mt][j][2], c[mt][j][3]);
        }
    }
}

// ---------------- aggregation: warp per node, CSR gather -------------------
__global__ void agg_kernel(const float* __restrict__ bias, int n) {
    int gw   = (blockIdx.x * blockDim.x + threadIdx.x) >> 5;
    int lane = threadIdx.x & 31;
    if (gw >= n) return;
    const float4* base = (const float4*)g_h;
    float di = g_dinv[gw];
    float w0 = di * di;
    float4 v = __ldg(&base[(size_t)gw * 32 + lane]);
    float4 acc = make_float4(w0 * v.x, w0 * v.y, w0 * v.z, w0 * v.w);
    int s = g_start[gw], t = g_start[gw + 1];
    int e = s;
    for (; e + 1 < t; e += 2) {
        int   r0 = g_erow[e],     r1 = g_erow[e + 1];
        float n0 = g_enorm[e],    n1 = g_enorm[e + 1];
        float4 u0 = __ldg(&base[(size_t)r0 * 32 + lane]);
        float4 u1 = __ldg(&base[(size_t)r1 * 32 + lane]);
        acc.x += n0 * u0.x + n1 * u1.x;
        acc.y += n0 * u0.y + n1 * u1.y;
        acc.z += n0 * u0.z + n1 * u1.z;
        acc.w += n0 * u0.w + n1 * u1.w;
    }
    if (e < t) {
        int r = g_erow[e]; float w = g_enorm[e];
        float4 u = __ldg(&base[(size_t)r * 32 + lane]);
        acc.x += w * u.x; acc.y += w * u.y; acc.z += w * u.z; acc.w += w * u.w;
    }
    float4 b = __ldg(&((const float4*)bias)[lane]);
    acc.x += b.x; acc.y += b.y; acc.z += b.z; acc.w += b.w;
    ((float4*)g_t)[(size_t)gw * 32 + lane] = acc;
}

// ---------------- final projection: out[N,8] = g_t[N,128] @ Wfc + bfc ------
__global__ void fc_kernel(const float* __restrict__ Wfc,
                          const float* __restrict__ bfc, float* __restrict__ out, int n) {
    __shared__ float wsT[8 * 128];
    __shared__ float bs[8];
    for (int i = threadIdx.x; i < 1024; i += blockDim.x) {
        int k = i >> 3, c = i & 7;
        wsT[c * 128 + k] = Wfc[i];
    }
    if (threadIdx.x < 8) bs[threadIdx.x] = bfc[threadIdx.x];
    __syncthreads();
    int gw   = (blockIdx.x * blockDim.x + threadIdx.x) >> 5;
    int lane = threadIdx.x & 31;
    if (gw >= n) return;
    float4 v = ((const float4*)g_t)[(size_t)gw * 32 + lane];
#pragma unroll
    for (int c = 0; c < 8; c++) {
        float4 w = *(const float4*)&wsT[c * 128 + lane * 4];
        float p = v.x * w.x + v.y * w.y + v.z * w.z + v.w * w.w;
#pragma unroll
        for (int off = 16; off > 0; off >>= 1)
            p += __shfl_xor_sync(0xffffffffu, p, off);
        if (lane == 0) out[(size_t)gw * 8 + c] = p + bs[c];
    }
}

// ---------------- launch ----------------------------------------------------
extern "C" void kernel_launch(void* const* d_in, const int* in_sizes, int n_in,
                              void* d_out, int out_size) {
    const float* x   = (const float*)d_in[0];
    const void*  ei  = d_in[1];
    const float* W1  = (const float*)d_in[2];
    const float* b1  = (const float*)d_in[3];
    const float* W2  = (const float*)d_in[4];
    const float* b2  = (const float*)d_in[5];
    const float* Wfc = (const float*)d_in[6];
    const float* bfc = (const float*)d_in[7];
    float* out = (float*)d_out;

    int N = in_sizes[0] / FDIM;
    int E = in_sizes[1] / 2;
    int nb = (N + 511) / 512;

    int tB = 256;
    int gN = (N + tB - 1) / tB;
    int gE = (E + tB - 1) / tB;
    int gW = (N * 32 + tB - 1) / tB;
    int gM = (N + 127) / 128;

    cudaFuncSetAttribute(gemm_mma, cudaFuncAttributeMaxDynamicSharedMemorySize, SMEM_GEMM);

    detect_kernel<<<1, 256>>>((const int*)ei, E);
    hist_init<<<gN, tB>>>(N);
    hist_count<<<gE, tB>>>(ei, E);
    dinv_kernel<<<gN, tB>>>(N);
    scan_pass1<<<nb, 512>>>(N);
    scan_pass2<<<1, 32>>>(nb, N);
    scan_pass3<<<nb, 512>>>(N);           // also seeds g_fill
    fill_edges<<<gE, tB>>>(ei, E);
    prep_w<<<128, 256>>>(W1, W2);

    gemm_mma<<<gM, 256, SMEM_GEMM>>>(x, 0, 0, N);        // x @ W1 -> g_h
    agg_kernel<<<gW, tB>>>(b1, N);                       // g_h -> g_t (+b1)
    gemm_mma<<<gM, 256, SMEM_GEMM>>>(nullptr, 1, 1, N);  // g_t @ W2 -> g_h
    agg_kernel<<<gW, tB>>>(b2, N);                       // g_h -> g_t (+b2)
    fc_kernel<<<gW, tB>>>(Wfc, bfc, out, N);
}